// round 16
// baseline (speedup 1.0000x reference)
#include <cuda_runtime.h>
#include <cuda_bf16.h>
#include <cstdint>

// out[b,t] = sum_d x[b,t,d] * stimulus[b,t,d]
// B=8, T=8192, D=768 (fp32). HBM-bound streaming kernel — FINAL.
//
// Flat launch, one warp per row, 6 float4 per lane per stream, __ldcs
// (evict-first) since both streams are read-once. Warp-shuffle reduce.
// Best measured: 59.46us / DRAM 85.8% (~6.80 TB/s). Ten benched variants
// across five mechanisms (register MLP batching, persistent grids,
// multi-row warps, async-bulk one-shot, 2- and 3-stage cp.async.bulk
// pipelines) all plateau at 85-86% of spec HBM with issue at ~7% and
// compute pipes <4%: the memory system is the binding constraint. This is
// the sustained read ceiling for fp32 two-stream traffic on this part.

static constexpr int D = 768;
static constexpr int VEC_PER_ROW = D / 4;              // 192 float4
static constexpr int VEC_PER_LANE = VEC_PER_ROW / 32;  // 6

__global__ void __launch_bounds__(256)
dot_rows_kernel(const float4* __restrict__ x,
                const float4* __restrict__ s,
                float* __restrict__ out,
                int n_rows)
{
    const int warp_in_block = threadIdx.x >> 5;
    const int lane = threadIdx.x & 31;
    const int row = blockIdx.x * (blockDim.x >> 5) + warp_in_block;
    if (row >= n_rows) return;

    const float4* xr = x + (size_t)row * VEC_PER_ROW;
    const float4* sr = s + (size_t)row * VEC_PER_ROW;

    float4 a[VEC_PER_LANE];
    float4 b[VEC_PER_LANE];
#pragma unroll
    for (int i = 0; i < VEC_PER_LANE; ++i)
        a[i] = __ldcs(xr + lane + i * 32);
#pragma unroll
    for (int i = 0; i < VEC_PER_LANE; ++i)
        b[i] = __ldcs(sr + lane + i * 32);

    float acc = 0.0f;
#pragma unroll
    for (int i = 0; i < VEC_PER_LANE; ++i) {
        acc = fmaf(a[i].x, b[i].x, acc);
        acc = fmaf(a[i].y, b[i].y, acc);
        acc = fmaf(a[i].z, b[i].z, acc);
        acc = fmaf(a[i].w, b[i].w, acc);
    }

    // warp tree reduce
#pragma unroll
    for (int off = 16; off > 0; off >>= 1)
        acc += __shfl_xor_sync(0xFFFFFFFFu, acc, off);

    if (lane == 0)
        out[row] = acc;
}

extern "C" void kernel_launch(void* const* d_in, const int* in_sizes, int n_in,
                              void* d_out, int out_size)
{
    const float4* x = (const float4*)d_in[0];
    const float4* s = (const float4*)d_in[1];
    float* out = (float*)d_out;

    const int n_rows = out_size;           // B*T = 65536
    const int warps_per_block = 8;         // 256 threads
    const int blocks = (n_rows + warps_per_block - 1) / warps_per_block;

    dot_rows_kernel<<<blocks, 256>>>(x, s, out, n_rows);
}